// round 2
// baseline (speedup 1.0000x reference)
#include <cuda_runtime.h>
#include <math.h>
#include <stdint.h>

#define HQ   32
#define HKV  8
#define DH   128
#define HID  4096
#define IM   12288
#define SEQ  8192
#define EPSR 1e-6f

// ---------------- scratch (device globals; no allocation allowed) ----------
__device__ __align__(16) float g_h[HID];              // ln1 output
__device__ __align__(16) float g_qkv[HQ*DH + 2*HKV*DH]; // q | k | v raw projections
__device__ __align__(16) float g_q[HQ*DH];            // q after norm + rope
__device__ __align__(16) float g_attn[HQ*DH];         // attention output
__device__ __align__(16) float g_h1[HID];             // residual + o_proj
__device__ __align__(16) float g_h2[HID];             // ln2 output
__device__ __align__(16) float g_m[IM];               // silu(gate)*up

// ---------------- helpers --------------------------------------------------
__device__ __forceinline__ float warp_sum(float v) {
    #pragma unroll
    for (int o = 16; o; o >>= 1) v += __shfl_xor_sync(0xffffffffu, v, o);
    return v;
}

// ---------------- RMSNorm (single block) -----------------------------------
__global__ void rmsnorm_k(const float* __restrict__ x, const float* __restrict__ w,
                          float* __restrict__ out, int n) {
    __shared__ float red[32];
    float s = 0.f;
    for (int i = threadIdx.x; i < n; i += blockDim.x) { float v = x[i]; s += v * v; }
    s = warp_sum(s);
    if ((threadIdx.x & 31) == 0) red[threadIdx.x >> 5] = s;
    __syncthreads();
    if (threadIdx.x < 32) {
        float v = (threadIdx.x < (blockDim.x >> 5)) ? red[threadIdx.x] : 0.f;
        v = warp_sum(v);
        if (threadIdx.x == 0) red[0] = v;
    }
    __syncthreads();
    float inv = rsqrtf(red[0] / (float)n + EPSR);
    for (int i = threadIdx.x; i < n; i += blockDim.x) out[i] = x[i] * inv * w[i];
}

// ---------------- fused QKV GEMV: one warp per output row ------------------
__global__ void gemv_qkv_k(const float* __restrict__ Wq, const float* __restrict__ Wk,
                           const float* __restrict__ Wv) {
    int r = blockIdx.x * (blockDim.x >> 5) + (threadIdx.x >> 5);
    int lane = threadIdx.x & 31;
    const float* row;
    if (r < HID)                row = Wq + (size_t)r * HID;
    else if (r < HID + HKV*DH)  row = Wk + (size_t)(r - HID) * HID;
    else                        row = Wv + (size_t)(r - HID - HKV*DH) * HID;
    const float4* w4 = reinterpret_cast<const float4*>(row);
    const float4* x4 = reinterpret_cast<const float4*>(g_h);
    float s = 0.f;
    #pragma unroll 8
    for (int i = lane; i < HID/4; i += 32) {
        float4 a = __ldg(w4 + i); float4 b = x4[i];
        s += a.x*b.x + a.y*b.y + a.z*b.z + a.w*b.w;
    }
    s = warp_sum(s);
    if (lane == 0) g_qkv[r] = s;
}

// ---------------- per-head RMSNorm + RoPE; write KV cache row --------------
// blocks 0..HQ-1: q heads -> g_q.  blocks HQ..HQ+HKV-1: k heads -> cache; also v.
__global__ void qkrope_k(const float* __restrict__ cosv, const float* __restrict__ sinv,
                         const float* __restrict__ qw, const float* __restrict__ kw,
                         const float* __restrict__ posp,
                         float* __restrict__ out_k, float* __restrict__ out_v) {
    __shared__ float sh[DH];
    __shared__ float red[4];
    int t = threadIdx.x;                 // 0..127
    bool isq = blockIdx.x < HQ;
    int head = isq ? blockIdx.x : blockIdx.x - HQ;
    float v = isq ? g_qkv[head*DH + t] : g_qkv[HQ*DH + head*DH + t];
    float s = warp_sum(v * v);
    if ((t & 31) == 0) red[t >> 5] = s;
    __syncthreads();
    float tot = red[0] + red[1] + red[2] + red[3];
    float inv = rsqrtf(tot / (float)DH + EPSR);
    float nv = v * inv * (isq ? qw[t] : kw[t]);
    sh[t] = nv;
    __syncthreads();
    float partner = (t < DH/2) ? -sh[t + DH/2] : sh[t - DH/2];
    float r = nv * cosv[t] + partner * sinv[t];
    if (isq) {
        g_q[head*DH + t] = r;
    } else {
        int p = (int)posp[0];
        size_t off = (size_t)head * SEQ * DH + (size_t)p * DH + t;
        out_k[off] = r;
        out_v[off] = g_qkv[HQ*DH + HKV*DH + head*DH + t];
    }
}

// ---------------- GQA flash attention: one block per q head ----------------
// 8 warps split the key range; each keeps a local online softmax; merge in smem.
__global__ void attn_k(const float* __restrict__ posp,
                       const float* __restrict__ Kc, const float* __restrict__ Vc) {
    const float scale = 0.088388347648318447f;  // 128^-0.5
    int qh = blockIdx.x;
    int kv = qh >> 2;
    int warp = threadIdx.x >> 5, lane = threadIdx.x & 31;
    int p = (int)posp[0];
    const float* K = Kc + (size_t)kv * SEQ * DH;
    const float* V = Vc + (size_t)kv * SEQ * DH;
    float4 q = *(reinterpret_cast<const float4*>(g_q + qh*DH) + lane);

    float m = -INFINITY, l = 0.f;
    float4 acc = make_float4(0.f, 0.f, 0.f, 0.f);
    for (int j = warp; j <= p; j += 8) {
        float4 kx = __ldg(reinterpret_cast<const float4*>(K + (size_t)j * DH) + lane);
        float d = q.x*kx.x + q.y*kx.y + q.z*kx.z + q.w*kx.w;
        d = warp_sum(d) * scale;
        float mn = fmaxf(m, d);
        float corr = expf(m - mn);       // m=-inf first iter -> 0
        float w = expf(d - mn);
        l = l * corr + w;
        float4 vx = __ldg(reinterpret_cast<const float4*>(V + (size_t)j * DH) + lane);
        acc.x = acc.x * corr + w * vx.x;
        acc.y = acc.y * corr + w * vx.y;
        acc.z = acc.z * corr + w * vx.z;
        acc.w = acc.w * corr + w * vx.w;
        m = mn;
    }
    __shared__ float s_m[8], s_l[8];
    __shared__ float s_acc[8][DH];
    if (lane == 0) { s_m[warp] = m; s_l[warp] = l; }
    s_acc[warp][4*lane + 0] = acc.x;
    s_acc[warp][4*lane + 1] = acc.y;
    s_acc[warp][4*lane + 2] = acc.z;
    s_acc[warp][4*lane + 3] = acc.w;
    __syncthreads();
    if (threadIdx.x < DH) {
        int d = threadIdx.x;
        float M = -INFINITY;
        #pragma unroll
        for (int w = 0; w < 8; w++) M = fmaxf(M, s_m[w]);
        float L = 0.f, A = 0.f;
        #pragma unroll
        for (int w = 0; w < 8; w++) {
            float f = expf(s_m[w] - M);   // -inf warps contribute 0
            L += s_l[w] * f;
            A += s_acc[w][d] * f;
        }
        g_attn[qh*DH + d] = A / L;
    }
}

// ---------------- O projection + residual ----------------------------------
__global__ void gemv_o_k(const float* __restrict__ Wo, const float* __restrict__ resid) {
    int r = blockIdx.x * (blockDim.x >> 5) + (threadIdx.x >> 5);
    int lane = threadIdx.x & 31;
    const float4* w4 = reinterpret_cast<const float4*>(Wo + (size_t)r * (HQ*DH));
    const float4* x4 = reinterpret_cast<const float4*>(g_attn);
    float s = 0.f;
    #pragma unroll 8
    for (int i = lane; i < (HQ*DH)/4; i += 32) {
        float4 a = __ldg(w4 + i); float4 b = x4[i];
        s += a.x*b.x + a.y*b.y + a.z*b.z + a.w*b.w;
    }
    s = warp_sum(s);
    if (lane == 0) g_h1[r] = resid[r] + s;
}

// ---------------- gate + up GEMV (fused, one warp per row) -----------------
__global__ void gemv_gateup_k(const float* __restrict__ Wg, const float* __restrict__ Wu) {
    int r = blockIdx.x * (blockDim.x >> 5) + (threadIdx.x >> 5);
    int lane = threadIdx.x & 31;
    const float4* g4 = reinterpret_cast<const float4*>(Wg + (size_t)r * HID);
    const float4* u4 = reinterpret_cast<const float4*>(Wu + (size_t)r * HID);
    const float4* x4 = reinterpret_cast<const float4*>(g_h2);
    float sg = 0.f, su = 0.f;
    #pragma unroll 4
    for (int i = lane; i < HID/4; i += 32) {
        float4 b = x4[i];
        float4 a = __ldg(g4 + i);
        float4 c = __ldg(u4 + i);
        sg += a.x*b.x + a.y*b.y + a.z*b.z + a.w*b.w;
        su += c.x*b.x + c.y*b.y + c.z*b.z + c.w*b.w;
    }
    sg = warp_sum(sg);
    su = warp_sum(su);
    if (lane == 0) g_m[r] = (sg / (1.f + expf(-sg))) * su;
}

// ---------------- down GEMV + residual -> final hidden output --------------
__global__ void gemv_down_k(const float* __restrict__ Wd, float* __restrict__ out) {
    int r = blockIdx.x * (blockDim.x >> 5) + (threadIdx.x >> 5);
    int lane = threadIdx.x & 31;
    const float4* w4 = reinterpret_cast<const float4*>(Wd + (size_t)r * IM);
    const float4* x4 = reinterpret_cast<const float4*>(g_m);
    float s = 0.f;
    #pragma unroll 8
    for (int i = lane; i < IM/4; i += 32) {
        float4 a = __ldg(w4 + i); float4 b = x4[i];
        s += a.x*b.x + a.y*b.y + a.z*b.z + a.w*b.w;
    }
    s = warp_sum(s);
    if (lane == 0) out[r] = g_h1[r] + s;
}

// ---------------- launch ----------------------------------------------------
extern "C" void kernel_launch(void* const* d_in, const int* in_sizes, int n_in,
                              void* d_out, int out_size) {
    const float* x      = (const float*)d_in[0];   // hidden_conv (4096)
    const float* pos    = (const float*)d_in[1];   // position (1)
    const float* cosv   = (const float*)d_in[2];   // (128)
    const float* sinv   = (const float*)d_in[3];   // (128)
    const float* kcache = (const float*)d_in[4];   // (8*8192*128)
    const float* vcache = (const float*)d_in[5];
    const float* Wq     = (const float*)d_in[6];
    const float* Wk     = (const float*)d_in[7];
    const float* Wv     = (const float*)d_in[8];
    const float* Wo     = (const float*)d_in[9];
    const float* Wg     = (const float*)d_in[10];
    const float* Wu     = (const float*)d_in[11];
    const float* Wd     = (const float*)d_in[12];
    const float* qnw    = (const float*)d_in[13];
    const float* knw    = (const float*)d_in[14];
    const float* ln1w   = (const float*)d_in[15];
    const float* ln2w   = (const float*)d_in[16];

    float* out   = (float*)d_out;
    float* out_k = out + HID;                         // k_new
    float* out_v = out_k + (size_t)HKV * SEQ * DH;    // v_new
    const size_t cache_bytes = (size_t)HKV * SEQ * DH * sizeof(float);

    // bulk cache copy (row `pos` overwritten afterwards by qkrope_k)
    cudaMemcpyAsync(out_k, kcache, cache_bytes, cudaMemcpyDeviceToDevice, 0);
    cudaMemcpyAsync(out_v, vcache, cache_bytes, cudaMemcpyDeviceToDevice, 0);

    float* d_h = nullptr, *d_h1 = nullptr, *d_h2 = nullptr;
    cudaGetSymbolAddress((void**)&d_h,  g_h);
    cudaGetSymbolAddress((void**)&d_h1, g_h1);
    cudaGetSymbolAddress((void**)&d_h2, g_h2);

    rmsnorm_k<<<1, 1024>>>(x, ln1w, d_h, HID);
    gemv_qkv_k<<<(HID + 2*HKV*DH) / 8, 256>>>(Wq, Wk, Wv);
    qkrope_k<<<HQ + HKV, DH>>>(cosv, sinv, qnw, knw, pos, out_k, out_v);
    attn_k<<<HQ, 256>>>(pos, out_k, out_v);
    gemv_o_k<<<HID / 8, 256>>>(Wo, x);
    rmsnorm_k<<<1, 1024>>>(d_h1, ln2w, d_h2, HID);
    gemv_gateup_k<<<IM / 8, 256>>>(Wg, Wu);
    gemv_down_k<<<HID / 8, 256>>>(Wd, out);
}

// round 3
// speedup vs baseline: 1.6397x; 1.6397x over previous
#include <cuda_runtime.h>
#include <math.h>
#include <stdint.h>

#define HQ   32
#define HKV  8
#define DH   128
#define HID  4096
#define IM   12288
#define SEQ  8192
#define EPSR 1e-6f
#define NSPL 32           // KV splits per head for flash decoding

// ---------------- scratch (device globals; no allocation allowed) ----------
__device__ __align__(16) float g_h[HID];                 // ln1 output
__device__ __align__(16) float g_qkv[HQ*DH + 2*HKV*DH];  // q | k | v raw projections
__device__ __align__(16) float g_q[HQ*DH];               // q after norm + rope
__device__ __align__(16) float g_attn[HQ*DH];            // attention output
__device__ __align__(16) float g_h1[HID];                // residual + o_proj
__device__ __align__(16) float g_h2[HID];                // ln2 output
__device__ __align__(16) float g_m[IM];                  // silu(gate)*up
// split-KV partials
__device__ __align__(16) float g_pacc[HQ*NSPL*DH];
__device__ float g_pm[HQ*NSPL];
__device__ float g_pl[HQ*NSPL];

// ---------------- helpers --------------------------------------------------
__device__ __forceinline__ float warp_sum(float v) {
    #pragma unroll
    for (int o = 16; o; o >>= 1) v += __shfl_xor_sync(0xffffffffu, v, o);
    return v;
}

// ---------------- RMSNorm (single block) -----------------------------------
__global__ void rmsnorm_k(const float* __restrict__ x, const float* __restrict__ w,
                          float* __restrict__ out, int n) {
    __shared__ float red[32];
    float s = 0.f;
    for (int i = threadIdx.x; i < n; i += blockDim.x) { float v = x[i]; s += v * v; }
    s = warp_sum(s);
    if ((threadIdx.x & 31) == 0) red[threadIdx.x >> 5] = s;
    __syncthreads();
    if (threadIdx.x < 32) {
        float v = (threadIdx.x < (blockDim.x >> 5)) ? red[threadIdx.x] : 0.f;
        v = warp_sum(v);
        if (threadIdx.x == 0) red[0] = v;
    }
    __syncthreads();
    float inv = rsqrtf(red[0] / (float)n + EPSR);
    for (int i = threadIdx.x; i < n; i += blockDim.x) out[i] = x[i] * inv * w[i];
}

// ---------------- fused QKV GEMV: one warp per output row ------------------
__global__ void gemv_qkv_k(const float* __restrict__ Wq, const float* __restrict__ Wk,
                           const float* __restrict__ Wv) {
    int r = blockIdx.x * (blockDim.x >> 5) + (threadIdx.x >> 5);
    int lane = threadIdx.x & 31;
    const float* row;
    if (r < HID)                row = Wq + (size_t)r * HID;
    else if (r < HID + HKV*DH)  row = Wk + (size_t)(r - HID) * HID;
    else                        row = Wv + (size_t)(r - HID - HKV*DH) * HID;
    const float4* w4 = reinterpret_cast<const float4*>(row);
    const float4* x4 = reinterpret_cast<const float4*>(g_h);
    float s = 0.f;
    #pragma unroll 8
    for (int i = lane; i < HID/4; i += 32) {
        float4 a = __ldg(w4 + i); float4 b = x4[i];
        s += a.x*b.x + a.y*b.y + a.z*b.z + a.w*b.w;
    }
    s = warp_sum(s);
    if (lane == 0) g_qkv[r] = s;
}

// ---------------- per-head RMSNorm + RoPE; write KV cache row --------------
__global__ void qkrope_k(const float* __restrict__ cosv, const float* __restrict__ sinv,
                         const float* __restrict__ qw, const float* __restrict__ kw,
                         const float* __restrict__ posp,
                         float* __restrict__ out_k, float* __restrict__ out_v) {
    __shared__ float sh[DH];
    __shared__ float red[4];
    int t = threadIdx.x;                 // 0..127
    bool isq = blockIdx.x < HQ;
    int head = isq ? blockIdx.x : blockIdx.x - HQ;
    float v = isq ? g_qkv[head*DH + t] : g_qkv[HQ*DH + head*DH + t];
    float s = warp_sum(v * v);
    if ((t & 31) == 0) red[t >> 5] = s;
    __syncthreads();
    float tot = red[0] + red[1] + red[2] + red[3];
    float inv = rsqrtf(tot / (float)DH + EPSR);
    float nv = v * inv * (isq ? qw[t] : kw[t]);
    sh[t] = nv;
    __syncthreads();
    float partner = (t < DH/2) ? -sh[t + DH/2] : sh[t - DH/2];
    float r = nv * cosv[t] + partner * sinv[t];
    if (isq) {
        g_q[head*DH + t] = r;
    } else {
        int p = (int)posp[0];
        size_t off = (size_t)head * SEQ * DH + (size_t)p * DH + t;
        out_k[off] = r;
        out_v[off] = g_qkv[HQ*DH + HKV*DH + head*DH + t];
    }
}

// ---------------- split-KV flash attention: partials -----------------------
// grid = HQ * NSPL; block = 256 (8 warps). Each block does its key chunk with
// per-warp online softmax, merges warps in smem, writes one (m,l,acc) partial.
__global__ void attn_part_k(const float* __restrict__ posp,
                            const float* __restrict__ Kc, const float* __restrict__ Vc) {
    const float scale = 0.088388347648318447f;  // 128^-0.5
    int qh = blockIdx.x / NSPL;
    int sp = blockIdx.x % NSPL;
    int kv = qh >> 2;
    int warp = threadIdx.x >> 5, lane = threadIdx.x & 31;
    int total = (int)posp[0] + 1;
    int chunk = (total + NSPL - 1) / NSPL;
    int beg = sp * chunk;
    int end = min(beg + chunk, total);
    const float* K = Kc + (size_t)kv * SEQ * DH;
    const float* V = Vc + (size_t)kv * SEQ * DH;
    float4 q = *(reinterpret_cast<const float4*>(g_q + qh*DH) + lane);

    float m = -INFINITY, l = 0.f;
    float4 acc = make_float4(0.f, 0.f, 0.f, 0.f);
    for (int j = beg + warp; j < end; j += 8) {
        float4 kx = __ldg(reinterpret_cast<const float4*>(K + (size_t)j * DH) + lane);
        float4 vx = __ldg(reinterpret_cast<const float4*>(V + (size_t)j * DH) + lane);
        float d = q.x*kx.x + q.y*kx.y + q.z*kx.z + q.w*kx.w;
        d = warp_sum(d) * scale;
        float mn = fmaxf(m, d);
        float corr = (m > -INFINITY) ? __expf(m - mn) : 0.f;
        float w = __expf(d - mn);
        l = l * corr + w;
        acc.x = acc.x * corr + w * vx.x;
        acc.y = acc.y * corr + w * vx.y;
        acc.z = acc.z * corr + w * vx.z;
        acc.w = acc.w * corr + w * vx.w;
        m = mn;
    }
    __shared__ float s_m[8], s_l[8];
    __shared__ float s_acc[8][DH];
    if (lane == 0) { s_m[warp] = m; s_l[warp] = l; }
    s_acc[warp][4*lane + 0] = acc.x;
    s_acc[warp][4*lane + 1] = acc.y;
    s_acc[warp][4*lane + 2] = acc.z;
    s_acc[warp][4*lane + 3] = acc.w;
    __syncthreads();
    if (threadIdx.x < DH) {
        int d = threadIdx.x;
        float M = -INFINITY;
        #pragma unroll
        for (int w = 0; w < 8; w++) M = fmaxf(M, s_m[w]);
        float L = 0.f, A = 0.f;
        #pragma unroll
        for (int w = 0; w < 8; w++) {
            float f = (s_m[w] > -INFINITY) ? __expf(s_m[w] - M) : 0.f;
            L += s_l[w] * f;
            A += s_acc[w][d] * f;
        }
        g_pacc[(size_t)blockIdx.x * DH + d] = A;
        if (d == 0) { g_pm[blockIdx.x] = M; g_pl[blockIdx.x] = L; }
    }
}

// ---------------- split merge: one block (128 thr) per head ----------------
__global__ void attn_merge_k() {
    int qh = blockIdx.x;
    int d = threadIdx.x;                 // 0..127
    float M = -INFINITY;
    #pragma unroll
    for (int s = 0; s < NSPL; s++) M = fmaxf(M, g_pm[qh*NSPL + s]);
    float L = 0.f, A = 0.f;
    #pragma unroll
    for (int s = 0; s < NSPL; s++) {
        float pm = g_pm[qh*NSPL + s];
        float f = (pm > -INFINITY) ? __expf(pm - M) : 0.f;
        L += g_pl[qh*NSPL + s] * f;
        A += g_pacc[(size_t)(qh*NSPL + s) * DH + d] * f;
    }
    g_attn[qh*DH + d] = A / L;
}

// ---------------- O projection + residual ----------------------------------
__global__ void gemv_o_k(const float* __restrict__ Wo, const float* __restrict__ resid) {
    int r = blockIdx.x * (blockDim.x >> 5) + (threadIdx.x >> 5);
    int lane = threadIdx.x & 31;
    const float4* w4 = reinterpret_cast<const float4*>(Wo + (size_t)r * (HQ*DH));
    const float4* x4 = reinterpret_cast<const float4*>(g_attn);
    float s = 0.f;
    #pragma unroll 8
    for (int i = lane; i < (HQ*DH)/4; i += 32) {
        float4 a = __ldg(w4 + i); float4 b = x4[i];
        s += a.x*b.x + a.y*b.y + a.z*b.z + a.w*b.w;
    }
    s = warp_sum(s);
    if (lane == 0) g_h1[r] = resid[r] + s;
}

// ---------------- gate + up GEMV (fused, one warp per row) -----------------
__global__ void gemv_gateup_k(const float* __restrict__ Wg, const float* __restrict__ Wu) {
    int r = blockIdx.x * (blockDim.x >> 5) + (threadIdx.x >> 5);
    int lane = threadIdx.x & 31;
    const float4* g4 = reinterpret_cast<const float4*>(Wg + (size_t)r * HID);
    const float4* u4 = reinterpret_cast<const float4*>(Wu + (size_t)r * HID);
    const float4* x4 = reinterpret_cast<const float4*>(g_h2);
    float sg = 0.f, su = 0.f;
    #pragma unroll 4
    for (int i = lane; i < HID/4; i += 32) {
        float4 b = x4[i];
        float4 a = __ldg(g4 + i);
        float4 c = __ldg(u4 + i);
        sg += a.x*b.x + a.y*b.y + a.z*b.z + a.w*b.w;
        su += c.x*b.x + c.y*b.y + c.z*b.z + c.w*b.w;
    }
    sg = warp_sum(sg);
    su = warp_sum(su);
    if (lane == 0) g_m[r] = (sg / (1.f + __expf(-sg))) * su;
}

// ---------------- down GEMV + residual -> final hidden output --------------
__global__ void gemv_down_k(const float* __restrict__ Wd, float* __restrict__ out) {
    int r = blockIdx.x * (blockDim.x >> 5) + (threadIdx.x >> 5);
    int lane = threadIdx.x & 31;
    const float4* w4 = reinterpret_cast<const float4*>(Wd + (size_t)r * IM);
    const float4* x4 = reinterpret_cast<const float4*>(g_m);
    float s = 0.f;
    #pragma unroll 8
    for (int i = lane; i < IM/4; i += 32) {
        float4 a = __ldg(w4 + i); float4 b = x4[i];
        s += a.x*b.x + a.y*b.y + a.z*b.z + a.w*b.w;
    }
    s = warp_sum(s);
    if (lane == 0) out[r] = g_h1[r] + s;
}

// ---------------- launch ----------------------------------------------------
extern "C" void kernel_launch(void* const* d_in, const int* in_sizes, int n_in,
                              void* d_out, int out_size) {
    const float* x      = (const float*)d_in[0];   // hidden_conv (4096)
    const float* pos    = (const float*)d_in[1];   // position (1)
    const float* cosv   = (const float*)d_in[2];   // (128)
    const float* sinv   = (const float*)d_in[3];   // (128)
    const float* kcache = (const float*)d_in[4];   // (8*8192*128)
    const float* vcache = (const float*)d_in[5];
    const float* Wq     = (const float*)d_in[6];
    const float* Wk     = (const float*)d_in[7];
    const float* Wv     = (const float*)d_in[8];
    const float* Wo     = (const float*)d_in[9];
    const float* Wg     = (const float*)d_in[10];
    const float* Wu     = (const float*)d_in[11];
    const float* Wd     = (const float*)d_in[12];
    const float* qnw    = (const float*)d_in[13];
    const float* knw    = (const float*)d_in[14];
    const float* ln1w   = (const float*)d_in[15];
    const float* ln2w   = (const float*)d_in[16];

    float* out   = (float*)d_out;
    float* out_k = out + HID;                         // k_new
    float* out_v = out_k + (size_t)HKV * SEQ * DH;    // v_new
    const size_t cache_bytes = (size_t)HKV * SEQ * DH * sizeof(float);

    // bulk cache copy (row `pos` overwritten afterwards by qkrope_k)
    cudaMemcpyAsync(out_k, kcache, cache_bytes, cudaMemcpyDeviceToDevice, 0);
    cudaMemcpyAsync(out_v, vcache, cache_bytes, cudaMemcpyDeviceToDevice, 0);

    float* d_h = nullptr, *d_h1 = nullptr, *d_h2 = nullptr;
    cudaGetSymbolAddress((void**)&d_h,  g_h);
    cudaGetSymbolAddress((void**)&d_h1, g_h1);
    cudaGetSymbolAddress((void**)&d_h2, g_h2);

    rmsnorm_k<<<1, 1024>>>(x, ln1w, d_h, HID);
    gemv_qkv_k<<<(HID + 2*HKV*DH) / 8, 256>>>(Wq, Wk, Wv);
    qkrope_k<<<HQ + HKV, DH>>>(cosv, sinv, qnw, knw, pos, out_k, out_v);
    attn_part_k<<<HQ * NSPL, 256>>>(pos, out_k, out_v);
    attn_merge_k<<<HQ, DH>>>();
    gemv_o_k<<<HID / 8, 256>>>(Wo, x);
    rmsnorm_k<<<1, 1024>>>(d_h1, ln2w, d_h2, HID);
    gemv_gateup_k<<<IM / 8, 256>>>(Wg, Wu);
    gemv_down_k<<<HID / 8, 256>>>(Wd, out);
}

// round 4
// speedup vs baseline: 1.6416x; 1.0012x over previous
#include <cuda_runtime.h>
#include <math.h>
#include <stdint.h>

#define HQ   32
#define HKV  8
#define DH   128
#define HID  4096
#define IM   12288
#define SEQ  8192
#define EPSR 1e-6f
#define NSPL 32           // KV splits per head for flash decoding

// ---------------- scratch (device globals; no allocation allowed) ----------
__device__ __align__(16) float g_qkv[HQ*DH + 2*HKV*DH];  // q | k | v raw projections
__device__ __align__(16) float g_q[HQ*DH];               // q after norm + rope
__device__ __align__(16) float g_knew[HKV*DH];           // new K row (post rope)
__device__ __align__(16) float g_vnew[HKV*DH];           // new V row
__device__ __align__(16) float g_attn[HQ*DH];            // attention output
__device__ __align__(16) float g_h1[HID];                // residual + o_proj
__device__ __align__(16) float g_m[IM];                  // silu(gate)*up
// split-KV partials
__device__ __align__(16) float g_pacc[HQ*NSPL*DH];
__device__ float g_pm[HQ*NSPL];
__device__ float g_pl[HQ*NSPL];

// ---------------- helpers --------------------------------------------------
__device__ __forceinline__ float warp_sum(float v) {
    #pragma unroll
    for (int o = 16; o; o >>= 1) v += __shfl_xor_sync(0xffffffffu, v, o);
    return v;
}

// ============ fused RMSNorm + QKV GEMV =====================================
// block = 256 (8 warps), 8 rows/block. Stage x*lnw in smem; apply inv at end.
__global__ void gemv_qkv_k(const float* __restrict__ x, const float* __restrict__ lnw,
                           const float* __restrict__ Wq, const float* __restrict__ Wk,
                           const float* __restrict__ Wv) {
    __shared__ float4 sx[HID/4];
    __shared__ float red[8];
    int tid = threadIdx.x, warp = tid >> 5, lane = tid & 31;
    const float4* x4 = reinterpret_cast<const float4*>(x);
    const float4* w4 = reinterpret_cast<const float4*>(lnw);
    float ssq = 0.f;
    #pragma unroll
    for (int i = tid; i < HID/4; i += 256) {
        float4 v = __ldg(x4 + i);
        float4 w = __ldg(w4 + i);
        ssq += v.x*v.x + v.y*v.y + v.z*v.z + v.w*v.w;
        sx[i] = make_float4(v.x*w.x, v.y*w.y, v.z*w.z, v.w*w.w);
    }
    ssq = warp_sum(ssq);
    if (lane == 0) red[warp] = ssq;
    __syncthreads();

    int r = blockIdx.x * 8 + warp;
    const float* row;
    if (r < HQ*DH)                  row = Wq + (size_t)r * HID;
    else if (r < HQ*DH + HKV*DH)    row = Wk + (size_t)(r - HQ*DH) * HID;
    else                            row = Wv + (size_t)(r - HQ*DH - HKV*DH) * HID;
    const float4* wr = reinterpret_cast<const float4*>(row);
    float s = 0.f;
    #pragma unroll 8
    for (int i = lane; i < HID/4; i += 32) {
        float4 a = __ldg(wr + i); float4 b = sx[i];
        s += a.x*b.x + a.y*b.y + a.z*b.z + a.w*b.w;
    }
    s = warp_sum(s);
    if (lane == 0) {
        float tot = red[0]+red[1]+red[2]+red[3]+red[4]+red[5]+red[6]+red[7];
        g_qkv[r] = s * rsqrtf(tot / (float)HID + EPSR);
    }
}

// ---------------- per-head RMSNorm + RoPE ----------------------------------
// blocks 0..HQ-1: q heads -> g_q.  blocks HQ..HQ+HKV-1: k/v heads -> scratch.
__global__ void qkrope_k(const float* __restrict__ cosv, const float* __restrict__ sinv,
                         const float* __restrict__ qw, const float* __restrict__ kw) {
    __shared__ float sh[DH];
    __shared__ float red[4];
    int t = threadIdx.x;                 // 0..127
    bool isq = blockIdx.x < HQ;
    int head = isq ? blockIdx.x : blockIdx.x - HQ;
    float v = isq ? g_qkv[head*DH + t] : g_qkv[HQ*DH + head*DH + t];
    float s = warp_sum(v * v);
    if ((t & 31) == 0) red[t >> 5] = s;
    __syncthreads();
    float tot = red[0] + red[1] + red[2] + red[3];
    float inv = rsqrtf(tot / (float)DH + EPSR);
    float nv = v * inv * (isq ? qw[t] : kw[t]);
    sh[t] = nv;
    __syncthreads();
    float partner = (t < DH/2) ? -sh[t + DH/2] : sh[t - DH/2];
    float r = nv * cosv[t] + partner * sinv[t];
    if (isq) {
        g_q[head*DH + t] = r;
    } else {
        g_knew[head*DH + t] = r;
        g_vnew[head*DH + t] = g_qkv[HQ*DH + HKV*DH + head*DH + t];
    }
}

// ---------------- split-KV flash attention over ORIGINAL cache -------------
// Row `pos` is substituted from g_knew/g_vnew so attention has no dependency
// on the bulk cache copy (which runs on a parallel stream).
__global__ void attn_part_k(const float* __restrict__ posp,
                            const float* __restrict__ Kc, const float* __restrict__ Vc) {
    const float scale = 0.088388347648318447f;  // 128^-0.5
    int qh = blockIdx.x / NSPL;
    int sp = blockIdx.x % NSPL;
    int kv = qh >> 2;
    int warp = threadIdx.x >> 5, lane = threadIdx.x & 31;
    int p = (int)posp[0];
    int total = p + 1;
    int chunk = (total + NSPL - 1) / NSPL;
    int beg = sp * chunk;
    int end = min(beg + chunk, total);
    const float* K = Kc + (size_t)kv * SEQ * DH;
    const float* V = Vc + (size_t)kv * SEQ * DH;
    float4 q = *(reinterpret_cast<const float4*>(g_q + qh*DH) + lane);

    float m = -INFINITY, l = 0.f;
    float4 acc = make_float4(0.f, 0.f, 0.f, 0.f);
    for (int j = beg + warp; j < end; j += 8) {
        const float* krow = (j == p) ? (g_knew + kv*DH) : (K + (size_t)j * DH);
        const float* vrow = (j == p) ? (g_vnew + kv*DH) : (V + (size_t)j * DH);
        float4 kx = __ldg(reinterpret_cast<const float4*>(krow) + lane);
        float4 vx = __ldg(reinterpret_cast<const float4*>(vrow) + lane);
        float d = q.x*kx.x + q.y*kx.y + q.z*kx.z + q.w*kx.w;
        d = warp_sum(d) * scale;
        float mn = fmaxf(m, d);
        float corr = (m > -INFINITY) ? __expf(m - mn) : 0.f;
        float w = __expf(d - mn);
        l = l * corr + w;
        acc.x = acc.x * corr + w * vx.x;
        acc.y = acc.y * corr + w * vx.y;
        acc.z = acc.z * corr + w * vx.z;
        acc.w = acc.w * corr + w * vx.w;
        m = mn;
    }
    __shared__ float s_m[8], s_l[8];
    __shared__ float s_acc[8][DH];
    if (lane == 0) { s_m[warp] = m; s_l[warp] = l; }
    s_acc[warp][4*lane + 0] = acc.x;
    s_acc[warp][4*lane + 1] = acc.y;
    s_acc[warp][4*lane + 2] = acc.z;
    s_acc[warp][4*lane + 3] = acc.w;
    __syncthreads();
    if (threadIdx.x < DH) {
        int d = threadIdx.x;
        float M = -INFINITY;
        #pragma unroll
        for (int w = 0; w < 8; w++) M = fmaxf(M, s_m[w]);
        float L = 0.f, A = 0.f;
        #pragma unroll
        for (int w = 0; w < 8; w++) {
            float f = (s_m[w] > -INFINITY) ? __expf(s_m[w] - M) : 0.f;
            L += s_l[w] * f;
            A += s_acc[w][d] * f;
        }
        g_pacc[(size_t)blockIdx.x * DH + d] = A;
        if (d == 0) { g_pm[blockIdx.x] = M; g_pl[blockIdx.x] = L; }
    }
}

// ---------------- split merge: one block (128 thr) per head ----------------
__global__ void attn_merge_k() {
    int qh = blockIdx.x;
    int d = threadIdx.x;                 // 0..127
    float M = -INFINITY;
    #pragma unroll
    for (int s = 0; s < NSPL; s++) M = fmaxf(M, g_pm[qh*NSPL + s]);
    float L = 0.f, A = 0.f;
    #pragma unroll
    for (int s = 0; s < NSPL; s++) {
        float pm = g_pm[qh*NSPL + s];
        float f = (pm > -INFINITY) ? __expf(pm - M) : 0.f;
        L += g_pl[qh*NSPL + s] * f;
        A += g_pacc[(size_t)(qh*NSPL + s) * DH + d] * f;
    }
    g_attn[qh*DH + d] = A / L;
}

// ---------------- O projection + residual ----------------------------------
__global__ void gemv_o_k(const float* __restrict__ Wo, const float* __restrict__ resid) {
    __shared__ float4 sx[(HQ*DH)/4];
    int tid = threadIdx.x, warp = tid >> 5, lane = tid & 31;
    const float4* a4 = reinterpret_cast<const float4*>(g_attn);
    #pragma unroll
    for (int i = tid; i < (HQ*DH)/4; i += 256) sx[i] = a4[i];
    __syncthreads();
    int r = blockIdx.x * 8 + warp;
    const float4* w4 = reinterpret_cast<const float4*>(Wo + (size_t)r * (HQ*DH));
    float s = 0.f;
    #pragma unroll 8
    for (int i = lane; i < (HQ*DH)/4; i += 32) {
        float4 a = __ldg(w4 + i); float4 b = sx[i];
        s += a.x*b.x + a.y*b.y + a.z*b.z + a.w*b.w;
    }
    s = warp_sum(s);
    if (lane == 0) g_h1[r] = resid[r] + s;
}

// ============ fused RMSNorm + gate/up GEMV =================================
__global__ void gemv_gateup_k(const float* __restrict__ lnw,
                              const float* __restrict__ Wg, const float* __restrict__ Wu) {
    __shared__ float4 sx[HID/4];
    __shared__ float red[8];
    int tid = threadIdx.x, warp = tid >> 5, lane = tid & 31;
    const float4* x4 = reinterpret_cast<const float4*>(g_h1);
    const float4* w4 = reinterpret_cast<const float4*>(lnw);
    float ssq = 0.f;
    #pragma unroll
    for (int i = tid; i < HID/4; i += 256) {
        float4 v = x4[i];
        float4 w = __ldg(w4 + i);
        ssq += v.x*v.x + v.y*v.y + v.z*v.z + v.w*v.w;
        sx[i] = make_float4(v.x*w.x, v.y*w.y, v.z*w.z, v.w*w.w);
    }
    ssq = warp_sum(ssq);
    if (lane == 0) red[warp] = ssq;
    __syncthreads();

    int r = blockIdx.x * 8 + warp;
    const float4* g4 = reinterpret_cast<const float4*>(Wg + (size_t)r * HID);
    const float4* u4 = reinterpret_cast<const float4*>(Wu + (size_t)r * HID);
    float sg = 0.f, su = 0.f;
    #pragma unroll 4
    for (int i = lane; i < HID/4; i += 32) {
        float4 b = sx[i];
        float4 a = __ldg(g4 + i);
        float4 c = __ldg(u4 + i);
        sg += a.x*b.x + a.y*b.y + a.z*b.z + a.w*b.w;
        su += c.x*b.x + c.y*b.y + c.z*b.z + c.w*b.w;
    }
    sg = warp_sum(sg);
    su = warp_sum(su);
    if (lane == 0) {
        float tot = red[0]+red[1]+red[2]+red[3]+red[4]+red[5]+red[6]+red[7];
        float inv = rsqrtf(tot / (float)HID + EPSR);
        sg *= inv; su *= inv;
        g_m[r] = (sg / (1.f + __expf(-sg))) * su;
    }
}

// ---------------- down GEMV + residual -> final hidden output --------------
__global__ void gemv_down_k(const float* __restrict__ Wd, float* __restrict__ out) {
    int r = blockIdx.x * (blockDim.x >> 5) + (threadIdx.x >> 5);
    int lane = threadIdx.x & 31;
    const float4* w4 = reinterpret_cast<const float4*>(Wd + (size_t)r * IM);
    const float4* x4 = reinterpret_cast<const float4*>(g_m);
    float s = 0.f;
    #pragma unroll 8
    for (int i = lane; i < IM/4; i += 32) {
        float4 a = __ldg(w4 + i); float4 b = x4[i];
        s += a.x*b.x + a.y*b.y + a.z*b.z + a.w*b.w;
    }
    s = warp_sum(s);
    if (lane == 0) out[r] = g_h1[r] + s;
}

// ---------------- patch row `pos` of the copied caches ---------------------
__global__ void patch_k(const float* __restrict__ posp,
                        float* __restrict__ out_k, float* __restrict__ out_v) {
    int i = threadIdx.x;                 // 0..1023 = HKV*DH
    int head = i >> 7, t = i & 127;
    int p = (int)posp[0];
    size_t off = (size_t)head * SEQ * DH + (size_t)p * DH + t;
    out_k[off] = g_knew[i];
    out_v[off] = g_vnew[i];
}

// ---------------- launch ----------------------------------------------------
extern "C" void kernel_launch(void* const* d_in, const int* in_sizes, int n_in,
                              void* d_out, int out_size) {
    const float* x      = (const float*)d_in[0];
    const float* pos    = (const float*)d_in[1];
    const float* cosv   = (const float*)d_in[2];
    const float* sinv   = (const float*)d_in[3];
    const float* kcache = (const float*)d_in[4];
    const float* vcache = (const float*)d_in[5];
    const float* Wq     = (const float*)d_in[6];
    const float* Wk     = (const float*)d_in[7];
    const float* Wv     = (const float*)d_in[8];
    const float* Wo     = (const float*)d_in[9];
    const float* Wg     = (const float*)d_in[10];
    const float* Wu     = (const float*)d_in[11];
    const float* Wd     = (const float*)d_in[12];
    const float* qnw    = (const float*)d_in[13];
    const float* knw    = (const float*)d_in[14];
    const float* ln1w   = (const float*)d_in[15];
    const float* ln2w   = (const float*)d_in[16];

    float* out   = (float*)d_out;
    float* out_k = out + HID;
    float* out_v = out_k + (size_t)HKV * SEQ * DH;
    const size_t cache_bytes = (size_t)HKV * SEQ * DH * sizeof(float);

    // One-time side-stream + events (created outside any capture; reused).
    static cudaStream_t s2 = nullptr;
    static cudaEvent_t ev_fork = nullptr, ev_join = nullptr;
    if (!s2) {
        cudaStreamCreateWithFlags(&s2, cudaStreamNonBlocking);
        cudaEventCreateWithFlags(&ev_fork, cudaEventDisableTiming);
        cudaEventCreateWithFlags(&ev_join, cudaEventDisableTiming);
    }

    // Fork: bulk cache copy runs concurrently with the whole compute pipeline.
    cudaEventRecord(ev_fork, 0);
    cudaStreamWaitEvent(s2, ev_fork, 0);
    cudaMemcpyAsync(out_k, kcache, cache_bytes, cudaMemcpyDeviceToDevice, s2);
    cudaMemcpyAsync(out_v, vcache, cache_bytes, cudaMemcpyDeviceToDevice, s2);
    cudaEventRecord(ev_join, s2);

    gemv_qkv_k<<<(HQ*DH + 2*HKV*DH) / 8, 256>>>(x, ln1w, Wq, Wk, Wv);
    qkrope_k<<<HQ + HKV, DH>>>(cosv, sinv, qnw, knw);
    attn_part_k<<<HQ * NSPL, 256>>>(pos, kcache, vcache);
    attn_merge_k<<<HQ, DH>>>();
    gemv_o_k<<<HID / 8, 256>>>(Wo, x);
    gemv_gateup_k<<<IM / 8, 256>>>(ln2w, Wg, Wu);
    gemv_down_k<<<HID / 8, 256>>>(Wd, out);

    // Join: patch the freshly written row into the copied caches.
    cudaStreamWaitEvent(0, ev_join, 0);
    patch_k<<<1, HKV * DH>>>(pos, out_k, out_v);
}

// round 5
// speedup vs baseline: 1.8058x; 1.1000x over previous
#include <cuda_runtime.h>
#include <math.h>
#include <stdint.h>

#define HQ   32
#define HKV  8
#define DH   128
#define HID  4096
#define IM   12288
#define SEQ  8192
#define EPSR 1e-6f
#define NSPL 32           // KV splits per head for flash decoding

// ---------------- scratch (device globals; no allocation allowed) ----------
__device__ __align__(16) float g_qkv[HQ*DH + 2*HKV*DH];  // q | k | v raw projections
__device__ __align__(16) float g_q[HQ*DH];               // q after norm + rope
__device__ __align__(16) float g_knew[HKV*DH];           // new K row (post rope)
__device__ __align__(16) float g_vnew[HKV*DH];           // new V row
__device__ __align__(16) float g_attn[HQ*DH];            // attention output
__device__ __align__(16) float g_h1[HID];                // residual + o_proj
__device__ __align__(16) float g_m[IM];                  // silu(gate)*up
// split-KV partials
__device__ __align__(16) float g_pacc[HQ*NSPL*DH];
__device__ float g_pm[HQ*NSPL];
__device__ float g_pl[HQ*NSPL];

// ---------------- helpers --------------------------------------------------
__device__ __forceinline__ float warp_sum(float v) {
    #pragma unroll
    for (int o = 16; o; o >>= 1) v += __shfl_xor_sync(0xffffffffu, v, o);
    return v;
}
__device__ __forceinline__ float warp_max(float v) {
    #pragma unroll
    for (int o = 16; o; o >>= 1) v = fmaxf(v, __shfl_xor_sync(0xffffffffu, v, o));
    return v;
}

// ============ fused RMSNorm + QKV GEMV =====================================
// block = 256 (8 warps), 8 rows/block. Stage x*lnw in smem; apply inv at end.
__global__ void gemv_qkv_k(const float* __restrict__ x, const float* __restrict__ lnw,
                           const float* __restrict__ Wq, const float* __restrict__ Wk,
                           const float* __restrict__ Wv) {
    __shared__ float4 sx[HID/4];
    __shared__ float red[8];
    int tid = threadIdx.x, warp = tid >> 5, lane = tid & 31;
    const float4* x4 = reinterpret_cast<const float4*>(x);
    const float4* w4 = reinterpret_cast<const float4*>(lnw);
    float ssq = 0.f;
    #pragma unroll
    for (int i = tid; i < HID/4; i += 256) {
        float4 v = __ldg(x4 + i);
        float4 w = __ldg(w4 + i);
        ssq += v.x*v.x + v.y*v.y + v.z*v.z + v.w*v.w;
        sx[i] = make_float4(v.x*w.x, v.y*w.y, v.z*w.z, v.w*w.w);
    }
    ssq = warp_sum(ssq);
    if (lane == 0) red[warp] = ssq;
    __syncthreads();

    int r = blockIdx.x * 8 + warp;
    const float* row;
    if (r < HQ*DH)                  row = Wq + (size_t)r * HID;
    else if (r < HQ*DH + HKV*DH)    row = Wk + (size_t)(r - HQ*DH) * HID;
    else                            row = Wv + (size_t)(r - HQ*DH - HKV*DH) * HID;
    const float4* wr = reinterpret_cast<const float4*>(row);
    float s = 0.f;
    #pragma unroll 8
    for (int i = lane; i < HID/4; i += 32) {
        float4 a = __ldcs(wr + i); float4 b = sx[i];
        s += a.x*b.x + a.y*b.y + a.z*b.z + a.w*b.w;
    }
    s = warp_sum(s);
    if (lane == 0) {
        float tot = red[0]+red[1]+red[2]+red[3]+red[4]+red[5]+red[6]+red[7];
        g_qkv[r] = s * rsqrtf(tot / (float)HID + EPSR);
    }
}

// ---------------- per-head RMSNorm + RoPE ----------------------------------
__global__ void qkrope_k(const float* __restrict__ cosv, const float* __restrict__ sinv,
                         const float* __restrict__ qw, const float* __restrict__ kw) {
    __shared__ float sh[DH];
    __shared__ float red[4];
    int t = threadIdx.x;                 // 0..127
    bool isq = blockIdx.x < HQ;
    int head = isq ? blockIdx.x : blockIdx.x - HQ;
    float v = isq ? g_qkv[head*DH + t] : g_qkv[HQ*DH + head*DH + t];
    float s = warp_sum(v * v);
    if ((t & 31) == 0) red[t >> 5] = s;
    __syncthreads();
    float tot = red[0] + red[1] + red[2] + red[3];
    float inv = rsqrtf(tot / (float)DH + EPSR);
    float nv = v * inv * (isq ? qw[t] : kw[t]);
    sh[t] = nv;
    __syncthreads();
    float partner = (t < DH/2) ? -sh[t + DH/2] : sh[t - DH/2];
    float r = nv * cosv[t] + partner * sinv[t];
    if (isq) {
        g_q[head*DH + t] = r;
    } else {
        g_knew[head*DH + t] = r;
        g_vnew[head*DH + t] = g_qkv[HQ*DH + HKV*DH + head*DH + t];
    }
}

// ---------------- split-KV flash attention over ORIGINAL cache -------------
// Batched-4 keys per warp iteration: 8 independent LDG.128 up front, 4
// independent dot-reductions, ONE online-softmax correction per batch.
__global__ void attn_part_k(const float* __restrict__ posp,
                            const float* __restrict__ Kc, const float* __restrict__ Vc) {
    const float scale = 0.088388347648318447f;  // 128^-0.5
    int qh = blockIdx.x / NSPL;
    int sp = blockIdx.x % NSPL;
    int kv = qh >> 2;
    int warp = threadIdx.x >> 5, lane = threadIdx.x & 31;
    int p = (int)posp[0];
    int total = p + 1;
    int chunk = (total + NSPL - 1) / NSPL;
    int beg = sp * chunk;
    int end = min(beg + chunk, total);
    const float* K = Kc + (size_t)kv * SEQ * DH;
    const float* V = Vc + (size_t)kv * SEQ * DH;
    float4 q = *(reinterpret_cast<const float4*>(g_q + qh*DH) + lane);

    float m = -INFINITY, l = 0.f;
    float4 acc = make_float4(0.f, 0.f, 0.f, 0.f);
    for (int base = beg; base < end; base += 32) {
        float4 kx[4], vx[4];
        bool val[4];
        #pragma unroll
        for (int t = 0; t < 4; t++) {
            int j = base + warp + 8*t;
            val[t] = (j < end);
            int jj = val[t] ? j : beg;
            const float* krow = (jj == p) ? (g_knew + kv*DH) : (K + (size_t)jj * DH);
            const float* vrow = (jj == p) ? (g_vnew + kv*DH) : (V + (size_t)jj * DH);
            kx[t] = __ldg(reinterpret_cast<const float4*>(krow) + lane);
            vx[t] = __ldg(reinterpret_cast<const float4*>(vrow) + lane);
        }
        float d[4];
        #pragma unroll
        for (int t = 0; t < 4; t++)
            d[t] = q.x*kx[t].x + q.y*kx[t].y + q.z*kx[t].z + q.w*kx[t].w;
        #pragma unroll
        for (int o = 16; o; o >>= 1) {
            #pragma unroll
            for (int t = 0; t < 4; t++) d[t] += __shfl_xor_sync(0xffffffffu, d[t], o);
        }
        #pragma unroll
        for (int t = 0; t < 4; t++) d[t] = val[t] ? d[t] * scale : -INFINITY;
        float mb = fmaxf(fmaxf(d[0], d[1]), fmaxf(d[2], d[3]));
        if (mb > -INFINITY) {
            float mn = fmaxf(m, mb);
            float corr = (m > -INFINITY) ? __expf(m - mn) : 0.f;
            l *= corr;
            acc.x *= corr; acc.y *= corr; acc.z *= corr; acc.w *= corr;
            #pragma unroll
            for (int t = 0; t < 4; t++) {
                if (val[t]) {
                    float w = __expf(d[t] - mn);
                    l += w;
                    acc.x += w * vx[t].x; acc.y += w * vx[t].y;
                    acc.z += w * vx[t].z; acc.w += w * vx[t].w;
                }
            }
            m = mn;
        }
    }
    __shared__ float s_m[8], s_l[8];
    __shared__ float s_acc[8][DH];
    if (lane == 0) { s_m[warp] = m; s_l[warp] = l; }
    s_acc[warp][4*lane + 0] = acc.x;
    s_acc[warp][4*lane + 1] = acc.y;
    s_acc[warp][4*lane + 2] = acc.z;
    s_acc[warp][4*lane + 3] = acc.w;
    __syncthreads();
    if (threadIdx.x < DH) {
        int d = threadIdx.x;
        float M = -INFINITY;
        #pragma unroll
        for (int w = 0; w < 8; w++) M = fmaxf(M, s_m[w]);
        float L = 0.f, A = 0.f;
        #pragma unroll
        for (int w = 0; w < 8; w++) {
            float f = (s_m[w] > -INFINITY) ? __expf(s_m[w] - M) : 0.f;
            L += s_l[w] * f;
            A += s_acc[w][d] * f;
        }
        g_pacc[(size_t)blockIdx.x * DH + d] = A;
        if (d == 0) { g_pm[blockIdx.x] = M; g_pl[blockIdx.x] = L; }
    }
}

// ---------------- split merge: one warp per (head, d); lane per split ------
__global__ void attn_merge_k() {
    int gw = (blockIdx.x * blockDim.x + threadIdx.x) >> 5;  // 0..HQ*DH-1
    int lane = threadIdx.x & 31;
    int qh = gw >> 7, d = gw & 127;
    float pm = g_pm[qh*NSPL + lane];
    float pl = g_pl[qh*NSPL + lane];
    float pa = g_pacc[(size_t)(qh*NSPL + lane) * DH + d];
    float M = warp_max(pm);
    float f = (pm > -INFINITY) ? __expf(pm - M) : 0.f;
    float L = warp_sum(pl * f);
    float A = warp_sum(pa * f);
    if (lane == 0) g_attn[qh*DH + d] = A / L;
}

// ---------------- O projection + residual ----------------------------------
__global__ void gemv_o_k(const float* __restrict__ Wo, const float* __restrict__ resid) {
    __shared__ float4 sx[(HQ*DH)/4];
    int tid = threadIdx.x, warp = tid >> 5, lane = tid & 31;
    const float4* a4 = reinterpret_cast<const float4*>(g_attn);
    #pragma unroll
    for (int i = tid; i < (HQ*DH)/4; i += 256) sx[i] = a4[i];
    __syncthreads();
    int r = blockIdx.x * 8 + warp;
    const float4* w4 = reinterpret_cast<const float4*>(Wo + (size_t)r * (HQ*DH));
    float s = 0.f;
    #pragma unroll 8
    for (int i = lane; i < (HQ*DH)/4; i += 32) {
        float4 a = __ldcs(w4 + i); float4 b = sx[i];
        s += a.x*b.x + a.y*b.y + a.z*b.z + a.w*b.w;
    }
    s = warp_sum(s);
    if (lane == 0) g_h1[r] = resid[r] + s;
}

// ============ fused RMSNorm + gate/up GEMV =================================
__global__ void gemv_gateup_k(const float* __restrict__ lnw,
                              const float* __restrict__ Wg, const float* __restrict__ Wu) {
    __shared__ float4 sx[HID/4];
    __shared__ float red[8];
    int tid = threadIdx.x, warp = tid >> 5, lane = tid & 31;
    const float4* x4 = reinterpret_cast<const float4*>(g_h1);
    const float4* w4 = reinterpret_cast<const float4*>(lnw);
    float ssq = 0.f;
    #pragma unroll
    for (int i = tid; i < HID/4; i += 256) {
        float4 v = x4[i];
        float4 w = __ldg(w4 + i);
        ssq += v.x*v.x + v.y*v.y + v.z*v.z + v.w*v.w;
        sx[i] = make_float4(v.x*w.x, v.y*w.y, v.z*w.z, v.w*w.w);
    }
    ssq = warp_sum(ssq);
    if (lane == 0) red[warp] = ssq;
    __syncthreads();

    int r = blockIdx.x * 8 + warp;
    const float4* g4 = reinterpret_cast<const float4*>(Wg + (size_t)r * HID);
    const float4* u4 = reinterpret_cast<const float4*>(Wu + (size_t)r * HID);
    float sg = 0.f, su = 0.f;
    #pragma unroll 8
    for (int i = lane; i < HID/4; i += 32) {
        float4 b = sx[i];
        float4 a = __ldcs(g4 + i);
        float4 c = __ldcs(u4 + i);
        sg += a.x*b.x + a.y*b.y + a.z*b.z + a.w*b.w;
        su += c.x*b.x + c.y*b.y + c.z*b.z + c.w*b.w;
    }
    sg = warp_sum(sg);
    su = warp_sum(su);
    if (lane == 0) {
        float tot = red[0]+red[1]+red[2]+red[3]+red[4]+red[5]+red[6]+red[7];
        float inv = rsqrtf(tot / (float)HID + EPSR);
        sg *= inv; su *= inv;
        g_m[r] = (sg / (1.f + __expf(-sg))) * su;
    }
}

// ---------------- down GEMV + residual (x staged in 48KB smem) -------------
__global__ void gemv_down_k(const float* __restrict__ Wd, float* __restrict__ out) {
    __shared__ float4 sx[IM/4];          // 48 KB
    int tid = threadIdx.x, warp = tid >> 5, lane = tid & 31;
    const float4* m4 = reinterpret_cast<const float4*>(g_m);
    #pragma unroll
    for (int i = tid; i < IM/4; i += 256) sx[i] = m4[i];
    __syncthreads();
    int r = blockIdx.x * 8 + warp;
    const float4* w4 = reinterpret_cast<const float4*>(Wd + (size_t)r * IM);
    float s = 0.f;
    #pragma unroll 8
    for (int i = lane; i < IM/4; i += 32) {
        float4 a = __ldcs(w4 + i); float4 b = sx[i];
        s += a.x*b.x + a.y*b.y + a.z*b.z + a.w*b.w;
    }
    s = warp_sum(s);
    if (lane == 0) out[r] = g_h1[r] + s;
}

// ---------------- patch row `pos` of the copied caches ---------------------
__global__ void patch_k(const float* __restrict__ posp,
                        float* __restrict__ out_k, float* __restrict__ out_v) {
    int i = threadIdx.x;                 // 0..1023 = HKV*DH
    int head = i >> 7, t = i & 127;
    int p = (int)posp[0];
    size_t off = (size_t)head * SEQ * DH + (size_t)p * DH + t;
    out_k[off] = g_knew[i];
    out_v[off] = g_vnew[i];
}

// ---------------- launch ----------------------------------------------------
extern "C" void kernel_launch(void* const* d_in, const int* in_sizes, int n_in,
                              void* d_out, int out_size) {
    const float* x      = (const float*)d_in[0];
    const float* pos    = (const float*)d_in[1];
    const float* cosv   = (const float*)d_in[2];
    const float* sinv   = (const float*)d_in[3];
    const float* kcache = (const float*)d_in[4];
    const float* vcache = (const float*)d_in[5];
    const float* Wq     = (const float*)d_in[6];
    const float* Wk     = (const float*)d_in[7];
    const float* Wv     = (const float*)d_in[8];
    const float* Wo     = (const float*)d_in[9];
    const float* Wg     = (const float*)d_in[10];
    const float* Wu     = (const float*)d_in[11];
    const float* Wd     = (const float*)d_in[12];
    const float* qnw    = (const float*)d_in[13];
    const float* knw    = (const float*)d_in[14];
    const float* ln1w   = (const float*)d_in[15];
    const float* ln2w   = (const float*)d_in[16];

    float* out   = (float*)d_out;
    float* out_k = out + HID;
    float* out_v = out_k + (size_t)HKV * SEQ * DH;
    const size_t cache_bytes = (size_t)HKV * SEQ * DH * sizeof(float);

    static cudaStream_t s2 = nullptr;
    static cudaEvent_t ev_fork = nullptr, ev_join = nullptr;
    if (!s2) {
        cudaStreamCreateWithFlags(&s2, cudaStreamNonBlocking);
        cudaEventCreateWithFlags(&ev_fork, cudaEventDisableTiming);
        cudaEventCreateWithFlags(&ev_join, cudaEventDisableTiming);
    }

    // Fork: bulk cache copy runs concurrently with the whole compute pipeline.
    cudaEventRecord(ev_fork, 0);
    cudaStreamWaitEvent(s2, ev_fork, 0);
    cudaMemcpyAsync(out_k, kcache, cache_bytes, cudaMemcpyDeviceToDevice, s2);
    cudaMemcpyAsync(out_v, vcache, cache_bytes, cudaMemcpyDeviceToDevice, s2);
    cudaEventRecord(ev_join, s2);

    gemv_qkv_k<<<(HQ*DH + 2*HKV*DH) / 8, 256>>>(x, ln1w, Wq, Wk, Wv);
    qkrope_k<<<HQ + HKV, DH>>>(cosv, sinv, qnw, knw);
    attn_part_k<<<HQ * NSPL, 256>>>(pos, kcache, vcache);
    attn_merge_k<<<(HQ * DH) / 8, 256>>>();
    gemv_o_k<<<HID / 8, 256>>>(Wo, x);
    gemv_gateup_k<<<IM / 8, 256>>>(ln2w, Wg, Wu);
    gemv_down_k<<<HID / 8, 256>>>(Wd, out);

    // Join: patch the freshly written row into the copied caches.
    cudaStreamWaitEvent(0, ev_join, 0);
    patch_k<<<1, HKV * DH>>>(pos, out_k, out_v);
}

// round 6
// speedup vs baseline: 1.8428x; 1.0205x over previous
#include <cuda_runtime.h>
#include <math.h>
#include <stdint.h>

#define HQ   32
#define HKV  8
#define DH   128
#define HID  4096
#define IM   12288
#define SEQ  8192
#define EPSR 1e-6f
#define NSPL 16           // KV splits per head for flash decoding

// ---------------- scratch (device globals; no allocation allowed) ----------
__device__ __align__(16) float g_qkv[HQ*DH + 2*HKV*DH];  // q | k | v raw projections
__device__ __align__(16) float g_knew[HKV*DH];           // new K row (post rope)
__device__ __align__(16) float g_vnew[HKV*DH];           // new V row
__device__ __align__(16) float g_attn[HQ*DH];            // attention output
__device__ __align__(16) float g_h1[HID];                // residual + o_proj
__device__ __align__(16) float g_m[IM];                  // silu(gate)*up
// split-KV partials + completion counters
__device__ __align__(16) float g_pacc[HQ*NSPL*DH];
__device__ float g_pm[HQ*NSPL];
__device__ float g_pl[HQ*NSPL];
__device__ int   g_cnt[HQ];                              // zero-init; self-resetting

// ---------------- helpers --------------------------------------------------
__device__ __forceinline__ float warp_sum(float v) {
    #pragma unroll
    for (int o = 16; o; o >>= 1) v += __shfl_xor_sync(0xffffffffu, v, o);
    return v;
}

// ============ fused RMSNorm + QKV GEMV =====================================
__global__ void gemv_qkv_k(const float* __restrict__ x, const float* __restrict__ lnw,
                           const float* __restrict__ Wq, const float* __restrict__ Wk,
                           const float* __restrict__ Wv) {
    __shared__ float4 sx[HID/4];
    __shared__ float red[8];
    int tid = threadIdx.x, warp = tid >> 5, lane = tid & 31;
    const float4* x4 = reinterpret_cast<const float4*>(x);
    const float4* w4 = reinterpret_cast<const float4*>(lnw);
    float ssq = 0.f;
    #pragma unroll
    for (int i = tid; i < HID/4; i += 256) {
        float4 v = __ldg(x4 + i);
        float4 w = __ldg(w4 + i);
        ssq += v.x*v.x + v.y*v.y + v.z*v.z + v.w*v.w;
        sx[i] = make_float4(v.x*w.x, v.y*w.y, v.z*w.z, v.w*w.w);
    }
    ssq = warp_sum(ssq);
    if (lane == 0) red[warp] = ssq;
    __syncthreads();

    int r = blockIdx.x * 8 + warp;
    const float* row;
    if (r < HQ*DH)                  row = Wq + (size_t)r * HID;
    else if (r < HQ*DH + HKV*DH)    row = Wk + (size_t)(r - HQ*DH) * HID;
    else                            row = Wv + (size_t)(r - HQ*DH - HKV*DH) * HID;
    const float4* wr = reinterpret_cast<const float4*>(row);
    float s = 0.f;
    #pragma unroll 8
    for (int i = lane; i < HID/4; i += 32) {
        float4 a = __ldcs(wr + i); float4 b = sx[i];
        s += a.x*b.x + a.y*b.y + a.z*b.z + a.w*b.w;
    }
    s = warp_sum(s);
    if (lane == 0) {
        float tot = red[0]+red[1]+red[2]+red[3]+red[4]+red[5]+red[6]+red[7];
        g_qkv[r] = s * rsqrtf(tot / (float)HID + EPSR);
    }
}

// ============ attention: fused rope + split-KV partials + last-block merge =
// grid = HQ * NSPL, block = 256 (8 warps).
__global__ void attn_k(const float* __restrict__ posp,
                       const float* __restrict__ Kc, const float* __restrict__ Vc,
                       const float* __restrict__ cosv, const float* __restrict__ sinv,
                       const float* __restrict__ qw, const float* __restrict__ kw) {
    const float scale = 0.088388347648318447f;  // 128^-0.5
    int qh = blockIdx.x / NSPL;
    int sp = blockIdx.x % NSPL;
    int kv = qh >> 2;
    int tid = threadIdx.x;
    int warp = tid >> 5, lane = tid & 31;

    __shared__ __align__(16) float sq[DH], sk[DH], sv[DH];
    __shared__ float redq[4], redk[4];

    // ---- prologue: per-head RMSNorm + RoPE (threads 0-127: q, 128-255: k/v)
    int t = tid & 127;
    bool doq = tid < 128;
    float v = doq ? g_qkv[qh*DH + t] : g_qkv[HQ*DH + kv*DH + t];
    float ss = warp_sum(v * v);
    if (lane == 0) { if (doq) redq[warp] = ss; else redk[warp - 4] = ss; }
    if (!doq) sv[t] = g_qkv[HQ*DH + HKV*DH + kv*DH + t];
    __syncthreads();
    float tot = doq ? (redq[0]+redq[1]+redq[2]+redq[3])
                    : (redk[0]+redk[1]+redk[2]+redk[3]);
    float inv = rsqrtf(tot / (float)DH + EPSR);
    float nv = v * inv * (doq ? qw[t] : kw[t]);
    if (doq) sq[t] = nv; else sk[t] = nv;
    __syncthreads();
    float partner;
    if (doq) partner = (t < DH/2) ? -sq[t + DH/2] : sq[t - DH/2];
    else     partner = (t < DH/2) ? -sk[t + DH/2] : sk[t - DH/2];
    float roped = nv * cosv[t] + partner * sinv[t];
    __syncthreads();
    if (doq) sq[t] = roped; else sk[t] = roped;
    __syncthreads();
    if (sp == 0 && (qh & 3) == 0 && !doq) {
        g_knew[kv*DH + t] = roped;
        g_vnew[kv*DH + t] = sv[t];
    }

    // ---- split-KV mainloop (batched 4 keys per warp iteration)
    int p = (int)posp[0];
    int total = p + 1;
    int chunk = (total + NSPL - 1) / NSPL;
    int beg = sp * chunk;
    int end = min(beg + chunk, total);
    const float* K = Kc + (size_t)kv * SEQ * DH;
    const float* V = Vc + (size_t)kv * SEQ * DH;
    float4 q = reinterpret_cast<const float4*>(sq)[lane];

    float m = -INFINITY, l = 0.f;
    float4 acc = make_float4(0.f, 0.f, 0.f, 0.f);
    for (int base = beg; base < end; base += 32) {
        float4 kx[4], vx[4];
        bool val[4];
        #pragma unroll
        for (int tt = 0; tt < 4; tt++) {
            int j = base + warp + 8*tt;
            val[tt] = (j < end);
            int jj = val[tt] ? j : beg;
            if (jj == p) {
                kx[tt] = reinterpret_cast<const float4*>(sk)[lane];
                vx[tt] = reinterpret_cast<const float4*>(sv)[lane];
            } else {
                kx[tt] = __ldg(reinterpret_cast<const float4*>(K + (size_t)jj * DH) + lane);
                vx[tt] = __ldg(reinterpret_cast<const float4*>(V + (size_t)jj * DH) + lane);
            }
        }
        float d[4];
        #pragma unroll
        for (int tt = 0; tt < 4; tt++)
            d[tt] = q.x*kx[tt].x + q.y*kx[tt].y + q.z*kx[tt].z + q.w*kx[tt].w;
        #pragma unroll
        for (int o = 16; o; o >>= 1) {
            #pragma unroll
            for (int tt = 0; tt < 4; tt++) d[tt] += __shfl_xor_sync(0xffffffffu, d[tt], o);
        }
        #pragma unroll
        for (int tt = 0; tt < 4; tt++) d[tt] = val[tt] ? d[tt] * scale : -INFINITY;
        float mb = fmaxf(fmaxf(d[0], d[1]), fmaxf(d[2], d[3]));
        if (mb > -INFINITY) {
            float mn = fmaxf(m, mb);
            float corr = (m > -INFINITY) ? __expf(m - mn) : 0.f;
            l *= corr;
            acc.x *= corr; acc.y *= corr; acc.z *= corr; acc.w *= corr;
            #pragma unroll
            for (int tt = 0; tt < 4; tt++) {
                if (val[tt]) {
                    float w = __expf(d[tt] - mn);
                    l += w;
                    acc.x += w * vx[tt].x; acc.y += w * vx[tt].y;
                    acc.z += w * vx[tt].z; acc.w += w * vx[tt].w;
                }
            }
            m = mn;
        }
    }

    // ---- block-level merge of 8 warps -> one partial
    __shared__ float s_m[8], s_l[8];
    __shared__ float s_acc[8][DH];
    if (lane == 0) { s_m[warp] = m; s_l[warp] = l; }
    s_acc[warp][4*lane + 0] = acc.x;
    s_acc[warp][4*lane + 1] = acc.y;
    s_acc[warp][4*lane + 2] = acc.z;
    s_acc[warp][4*lane + 3] = acc.w;
    __syncthreads();
    if (tid < DH) {
        int d = tid;
        float M = -INFINITY;
        #pragma unroll
        for (int w = 0; w < 8; w++) M = fmaxf(M, s_m[w]);
        float L = 0.f, A = 0.f;
        #pragma unroll
        for (int w = 0; w < 8; w++) {
            float f = (s_m[w] > -INFINITY) ? __expf(s_m[w] - M) : 0.f;
            L += s_l[w] * f;
            A += s_acc[w][d] * f;
        }
        g_pacc[(size_t)blockIdx.x * DH + d] = A;
        if (d == 0) { g_pm[blockIdx.x] = M; g_pl[blockIdx.x] = L; }
    }

    // ---- last block for this head merges all splits
    __shared__ int s_merge;
    __threadfence();
    __syncthreads();
    if (tid == 0) {
        int old = atomicAdd(&g_cnt[qh], 1);
        s_merge = (old == NSPL - 1);
        if (s_merge) g_cnt[qh] = 0;      // reset for next graph replay
    }
    __syncthreads();
    if (s_merge) {
        __threadfence();
        if (tid < DH) {
            int d = tid;
            float M = -INFINITY;
            #pragma unroll
            for (int s = 0; s < NSPL; s++) M = fmaxf(M, g_pm[qh*NSPL + s]);
            float L = 0.f, A = 0.f;
            #pragma unroll
            for (int s = 0; s < NSPL; s++) {
                float pm = g_pm[qh*NSPL + s];
                float f = (pm > -INFINITY) ? __expf(pm - M) : 0.f;
                L += g_pl[qh*NSPL + s] * f;
                A += g_pacc[(size_t)(qh*NSPL + s) * DH + d] * f;
            }
            g_attn[qh*DH + d] = A / L;
        }
    }
}

// ---------------- O projection + residual ----------------------------------
__global__ void gemv_o_k(const float* __restrict__ Wo, const float* __restrict__ resid) {
    __shared__ float4 sx[(HQ*DH)/4];
    int tid = threadIdx.x, warp = tid >> 5, lane = tid & 31;
    const float4* a4 = reinterpret_cast<const float4*>(g_attn);
    #pragma unroll
    for (int i = tid; i < (HQ*DH)/4; i += 256) sx[i] = a4[i];
    __syncthreads();
    int r = blockIdx.x * 8 + warp;
    const float4* w4 = reinterpret_cast<const float4*>(Wo + (size_t)r * (HQ*DH));
    float s = 0.f;
    #pragma unroll 8
    for (int i = lane; i < (HQ*DH)/4; i += 32) {
        float4 a = __ldcs(w4 + i); float4 b = sx[i];
        s += a.x*b.x + a.y*b.y + a.z*b.z + a.w*b.w;
    }
    s = warp_sum(s);
    if (lane == 0) g_h1[r] = resid[r] + s;
}

// ============ fused RMSNorm + gate/up GEMV =================================
__global__ void gemv_gateup_k(const float* __restrict__ lnw,
                              const float* __restrict__ Wg, const float* __restrict__ Wu) {
    __shared__ float4 sx[HID/4];
    __shared__ float red[8];
    int tid = threadIdx.x, warp = tid >> 5, lane = tid & 31;
    const float4* x4 = reinterpret_cast<const float4*>(g_h1);
    const float4* w4 = reinterpret_cast<const float4*>(lnw);
    float ssq = 0.f;
    #pragma unroll
    for (int i = tid; i < HID/4; i += 256) {
        float4 v = x4[i];
        float4 w = __ldg(w4 + i);
        ssq += v.x*v.x + v.y*v.y + v.z*v.z + v.w*v.w;
        sx[i] = make_float4(v.x*w.x, v.y*w.y, v.z*w.z, v.w*w.w);
    }
    ssq = warp_sum(ssq);
    if (lane == 0) red[warp] = ssq;
    __syncthreads();

    int r = blockIdx.x * 8 + warp;
    const float4* g4 = reinterpret_cast<const float4*>(Wg + (size_t)r * HID);
    const float4* u4 = reinterpret_cast<const float4*>(Wu + (size_t)r * HID);
    float sg = 0.f, su = 0.f;
    #pragma unroll 8
    for (int i = lane; i < HID/4; i += 32) {
        float4 b = sx[i];
        float4 a = __ldcs(g4 + i);
        float4 c = __ldcs(u4 + i);
        sg += a.x*b.x + a.y*b.y + a.z*b.z + a.w*b.w;
        su += c.x*b.x + c.y*b.y + c.z*b.z + c.w*b.w;
    }
    sg = warp_sum(sg);
    su = warp_sum(su);
    if (lane == 0) {
        float tot = red[0]+red[1]+red[2]+red[3]+red[4]+red[5]+red[6]+red[7];
        float inv = rsqrtf(tot / (float)HID + EPSR);
        sg *= inv; su *= inv;
        g_m[r] = (sg / (1.f + __expf(-sg))) * su;
    }
}

// ---------------- down GEMV + residual (x staged in 48KB smem) -------------
__global__ void gemv_down_k(const float* __restrict__ Wd, float* __restrict__ out) {
    __shared__ float4 sx[IM/4];          // 48 KB
    int tid = threadIdx.x, warp = tid >> 5, lane = tid & 31;
    const float4* m4 = reinterpret_cast<const float4*>(g_m);
    #pragma unroll
    for (int i = tid; i < IM/4; i += 256) sx[i] = m4[i];
    __syncthreads();
    int r = blockIdx.x * 8 + warp;
    const float4* w4 = reinterpret_cast<const float4*>(Wd + (size_t)r * IM);
    float s = 0.f;
    #pragma unroll 8
    for (int i = lane; i < IM/4; i += 32) {
        float4 a = __ldcs(w4 + i); float4 b = sx[i];
        s += a.x*b.x + a.y*b.y + a.z*b.z + a.w*b.w;
    }
    s = warp_sum(s);
    if (lane == 0) out[r] = g_h1[r] + s;
}

// ---------------- patch row `pos` of the copied caches ---------------------
__global__ void patch_k(const float* __restrict__ posp,
                        float* __restrict__ out_k, float* __restrict__ out_v) {
    int i = threadIdx.x;                 // 0..1023 = HKV*DH
    int head = i >> 7, t = i & 127;
    int p = (int)posp[0];
    size_t off = (size_t)head * SEQ * DH + (size_t)p * DH + t;
    out_k[off] = g_knew[i];
    out_v[off] = g_vnew[i];
}

// ---------------- launch ----------------------------------------------------
extern "C" void kernel_launch(void* const* d_in, const int* in_sizes, int n_in,
                              void* d_out, int out_size) {
    const float* x      = (const float*)d_in[0];
    const float* pos    = (const float*)d_in[1];
    const float* cosv   = (const float*)d_in[2];
    const float* sinv   = (const float*)d_in[3];
    const float* kcache = (const float*)d_in[4];
    const float* vcache = (const float*)d_in[5];
    const float* Wq     = (const float*)d_in[6];
    const float* Wk     = (const float*)d_in[7];
    const float* Wv     = (const float*)d_in[8];
    const float* Wo     = (const float*)d_in[9];
    const float* Wg     = (const float*)d_in[10];
    const float* Wu     = (const float*)d_in[11];
    const float* Wd     = (const float*)d_in[12];
    const float* qnw    = (const float*)d_in[13];
    const float* knw    = (const float*)d_in[14];
    const float* ln1w   = (const float*)d_in[15];
    const float* ln2w   = (const float*)d_in[16];

    float* out   = (float*)d_out;
    float* out_k = out + HID;
    float* out_v = out_k + (size_t)HKV * SEQ * DH;
    const size_t cache_bytes = (size_t)HKV * SEQ * DH * sizeof(float);

    static cudaStream_t s2 = nullptr;
    static cudaEvent_t ev_fork = nullptr, ev_join = nullptr;
    if (!s2) {
        cudaStreamCreateWithFlags(&s2, cudaStreamNonBlocking);
        cudaEventCreateWithFlags(&ev_fork, cudaEventDisableTiming);
        cudaEventCreateWithFlags(&ev_join, cudaEventDisableTiming);
    }

    // Fork: bulk cache copy runs concurrently with the whole compute pipeline.
    cudaEventRecord(ev_fork, 0);
    cudaStreamWaitEvent(s2, ev_fork, 0);
    cudaMemcpyAsync(out_k, kcache, cache_bytes, cudaMemcpyDeviceToDevice, s2);
    cudaMemcpyAsync(out_v, vcache, cache_bytes, cudaMemcpyDeviceToDevice, s2);
    cudaEventRecord(ev_join, s2);

    gemv_qkv_k<<<(HQ*DH + 2*HKV*DH) / 8, 256>>>(x, ln1w, Wq, Wk, Wv);
    attn_k<<<HQ * NSPL, 256>>>(pos, kcache, vcache, cosv, sinv, qnw, knw);
    gemv_o_k<<<HID / 8, 256>>>(Wo, x);
    gemv_gateup_k<<<IM / 8, 256>>>(ln2w, Wg, Wu);
    gemv_down_k<<<HID / 8, 256>>>(Wd, out);

    // Join: patch the freshly written row into the copied caches.
    cudaStreamWaitEvent(0, ev_join, 0);
    patch_k<<<1, HKV * DH>>>(pos, out_k, out_v);
}